// round 1
// baseline (speedup 1.0000x reference)
#include <cuda_runtime.h>
#include <cuda_bf16.h>
#include <math.h>

// ---------------- problem constants ----------------
#define BATCH   8192
#define SEG     3200
#define NFFT    512
#define HOP     160
#define NFREQ   257
#define NFRM    17
#define SD      4369          // NFREQ*NFRM
#define NB      128
#define LAM     0.5f
#define ITERS   50

#define PI_F 3.14159265358979f

// ---------------- scratch (no allocation allowed) ----------------
__device__ float g_spec[(size_t)BATCH * SD];   // T-major: [b][t*257+f]  (~143 MB)
__device__ float g_stats[BATCH * 2];           // mean, invstd
__device__ float g_b[(size_t)BATCH * NB];
__device__ float g_gram[NB * NB];              // D D^T - I
__device__ float g_Dp[(size_t)NB * SD];        // D permuted to T-major
__device__ float g_sumD[NB];

// ---------------- D permute (F-major -> T-major) + row sums ----------------
__global__ void permuted_kernel(const float* __restrict__ D) {
    int j = blockIdx.x;
    int tid = threadIdx.x;
    const float* src = D + (size_t)j * SD;
    float* dst = g_Dp + (size_t)j * SD;
    float s = 0.f;
    for (int k = tid; k < SD; k += 256) {
        int t = k / NFREQ;
        int f = k - t * NFREQ;
        float v = src[f * NFRM + t];
        dst[k] = v;
        s += v;
    }
    __shared__ float red[256];
    red[tid] = s; __syncthreads();
    for (int o = 128; o > 0; o >>= 1) {
        if (tid < o) red[tid] += red[tid + o];
        __syncthreads();
    }
    if (tid == 0) g_sumD[j] = red[0];
}

// ---------------- gram = D D^T - I  (64 blocks of 16x16 outputs) ----------------
__global__ void gram_kernel(const float* __restrict__ D) {
    int ti = (blockIdx.x >> 3) * 16;
    int tj = (blockIdx.x & 7) * 16;
    int tid = threadIdx.x;            // 256
    int li = tid >> 4, lj = tid & 15;
    __shared__ float shi[16][65];
    __shared__ float shj[16][65];
    float acc = 0.f;
    int kk = tid & 63, r = tid >> 6;  // r in 0..3
    for (int k0 = 0; k0 < SD; k0 += 64) {
        int k = k0 + kk;
        bool ok = (k < SD);
        #pragma unroll
        for (int rr = 0; rr < 4; rr++) {
            int row = r + rr * 4;
            shi[row][kk] = ok ? D[(size_t)(ti + row) * SD + k] : 0.f;
            shj[row][kk] = ok ? D[(size_t)(tj + row) * SD + k] : 0.f;
        }
        __syncthreads();
        #pragma unroll 16
        for (int q = 0; q < 64; q++) acc += shi[li][q] * shj[lj][q];
        __syncthreads();
    }
    int i = ti + li, j = tj + lj;
    g_gram[i * NB + j] = acc - (i == j ? 1.f : 0.f);
}

// ---------------- STFT: 512-pt real FFT via packed 256-pt complex FFT ----------------
// one frame per 128-thread block; grid = (17, 8192)
__global__ void stft_kernel(const float* __restrict__ audio) {
    const int t = blockIdx.x;
    const int b = blockIdx.y;
    const int tid = threadIdx.x;     // 128
    __shared__ float sre[256];
    __shared__ float sim[256];

    const float* xp = audio + (size_t)b * SEG + t * HOP;
    const float W0 = 2.f * PI_F / (float)NFFT;

    // load + periodic-hann window + pack pairs + bit-reverse store
    #pragma unroll
    for (int p = tid; p < 256; p += 128) {
        float2 v = *(const float2*)(xp + 2 * p);
        int n0 = 2 * p;
        float w0 = 0.5f - 0.5f * __cosf(W0 * (float)n0);
        float w1 = 0.5f - 0.5f * __cosf(W0 * (float)(n0 + 1));
        int rix = __brev((unsigned)p) >> 24;   // 8-bit reverse
        sre[rix] = v.x * w0;
        sim[rix] = v.y * w1;
    }
    __syncthreads();

    // 8 radix-2 DIT stages (128 butterflies per stage, one per thread)
    #pragma unroll
    for (int s = 0; s < 8; s++) {
        int half = 1 << s;
        int pos = tid & (half - 1);
        int i0 = ((tid >> s) << (s + 1)) + pos;
        int i1 = i0 + half;
        float ang = -PI_F * (float)pos / (float)half;
        float wi, wr;
        __sincosf(ang, &wi, &wr);
        float ar = sre[i0], ai = sim[i0];
        float br = sre[i1], bi = sim[i1];
        float tr = br * wr - bi * wi;
        float ti2 = br * wi + bi * wr;
        sre[i0] = ar + tr;  sim[i0] = ai + ti2;
        sre[i1] = ar - tr;  sim[i1] = ai - ti2;
        __syncthreads();
    }

    // unpack real-FFT halves + magnitude; spec layout [b][t*257+f]
    float* out = g_spec + (size_t)b * SD + t * NFREQ;
    int k = tid;
    if (k == 0) {
        float re0 = sre[0], im0 = sim[0];
        out[0]   = fabsf(re0 + im0);
        out[256] = fabsf(re0 - im0);
        out[128] = sqrtf(sre[128] * sre[128] + sim[128] * sim[128]);
    } else {
        int mk = 256 - k;
        float zr = sre[k], zi = sim[k];
        float yr = sre[mk], yi = sim[mk];
        float er  = 0.5f * (zr + yr);
        float ei  = 0.5f * (zi - yi);
        float orr = 0.5f * (zi + yi);
        float oi  = -0.5f * (zr - yr);
        float ang = -PI_F * (float)k / 256.f;
        float ci, cr;
        __sincosf(ang, &ci, &cr);
        // X_k = E + W^k O
        float xr = er + cr * orr - ci * oi;
        float xi = ei + cr * oi + ci * orr;
        out[k] = sqrtf(xr * xr + xi * xi);
        // X_{256-k}: E' = (er, -ei); O' = (orr, -oi); W^{256-k} = (-cr, ci)
        float xr2 = er + (-cr) * orr - ci * (-oi);
        float xi2 = -ei + (-cr) * (-oi) + ci * orr;
        out[mk] = sqrtf(xr2 * xr2 + xi2 * xi2);
    }
}

// ---------------- per-sample mean / inv(std+1e-8), unbiased std ----------------
__global__ void stats_kernel() {
    int b = blockIdx.x;
    int tid = threadIdx.x;            // 256
    const float* row = g_spec + (size_t)b * SD;
    float s = 0.f, s2 = 0.f;
    for (int k = tid; k < SD; k += 256) {
        float v = row[k];
        s += v; s2 += v * v;
    }
    __shared__ float rs[256], r2[256];
    rs[tid] = s; r2[tid] = s2; __syncthreads();
    for (int o = 128; o > 0; o >>= 1) {
        if (tid < o) { rs[tid] += rs[tid + o]; r2[tid] += r2[tid + o]; }
        __syncthreads();
    }
    if (tid == 0) {
        float mean = rs[0] / (float)SD;
        float var = (r2[0] - (float)SD * mean * mean) / (float)(SD - 1);
        float sd = sqrtf(fmaxf(var, 0.f));
        g_stats[2 * b]     = mean;
        g_stats[2 * b + 1] = 1.f / (sd + 1e-8f);
    }
}

// ---------------- b = ((spec - mean)*invstd) @ D^T ----------------
// tile: 64 samples x 128 bases per block; 128 blocks, 256 threads
#define KC 32
__global__ void __launch_bounds__(256) bgemm_kernel() {
    __shared__ float sA[KC][68];    // [kk][s]
    __shared__ float sB[KC][132];   // [kk][j]
    int tid = threadIdx.x;
    int s0 = blockIdx.x * 64;
    int kk = tid & 31, rg = tid >> 5;
    int sl0 = (tid >> 4) * 4;
    int j0  = (tid & 15) * 8;
    float acc[4][8] = {};

    for (int k0 = 0; k0 < SD; k0 += KC) {
        int k = k0 + kk;
        bool ok = (k < SD);
        #pragma unroll
        for (int m = 0; m < 8; m++) {
            int ss = rg * 8 + m;
            sA[kk][ss] = ok ? g_spec[(size_t)(s0 + ss) * SD + k] : 0.f;
        }
        #pragma unroll
        for (int m = 0; m < 16; m++) {
            int j = rg * 16 + m;
            sB[kk][j] = ok ? g_Dp[(size_t)j * SD + k] : 0.f;
        }
        __syncthreads();
        #pragma unroll 8
        for (int q = 0; q < KC; q++) {
            float4 a  = *(const float4*)&sA[q][sl0];
            float4 b0 = *(const float4*)&sB[q][j0];
            float4 b1 = *(const float4*)&sB[q][j0 + 4];
            float av[4] = {a.x, a.y, a.z, a.w};
            float gv[8] = {b0.x, b0.y, b0.z, b0.w, b1.x, b1.y, b1.z, b1.w};
            #pragma unroll
            for (int ii = 0; ii < 4; ii++)
                #pragma unroll
                for (int jj = 0; jj < 8; jj++)
                    acc[ii][jj] += av[ii] * gv[jj];
        }
        __syncthreads();
    }
    #pragma unroll
    for (int ii = 0; ii < 4; ii++) {
        int s = s0 + sl0 + ii;
        float mean = g_stats[2 * s], inv = g_stats[2 * s + 1];
        #pragma unroll
        for (int jj = 0; jj < 8; jj++) {
            int j = j0 + jj;
            g_b[(size_t)s * NB + j] = (acc[ii][jj] - mean * g_sumD[j]) * inv;
        }
    }
}

// ---------------- LCA: 50 iterations, gram in shared, u/b in registers ----------------
// tile: 64 samples per block; 128 blocks, 256 threads, thread tile 4x8
__global__ void __launch_bounds__(256) lca_kernel(float* __restrict__ out) {
    extern __shared__ float smem[];
    float* sG = smem;                  // [128][132]
    float* sa = smem + 128 * 132;      // [64][132]
    int tid = threadIdx.x;
    int s0 = blockIdx.x * 64;

    for (int idx = tid; idx < NB * NB; idx += 256) {
        int i = idx >> 7, j = idx & 127;
        sG[i * 132 + j] = g_gram[idx];
    }

    int sl0 = (tid >> 4) * 4;
    int j0  = (tid & 15) * 8;
    float u[4][8], bb[4][8];
    #pragma unroll
    for (int ii = 0; ii < 4; ii++) {
        const float* bp = g_b + (size_t)(s0 + sl0 + ii) * NB + j0;
        #pragma unroll
        for (int jj = 0; jj < 8; jj++) { bb[ii][jj] = bp[jj]; u[ii][jj] = 0.f; }
    }
    __syncthreads();

    for (int it = 0; it < ITERS; it++) {
        // a = softshrink(u) -> shared
        #pragma unroll
        for (int ii = 0; ii < 4; ii++) {
            float* ap = &sa[(sl0 + ii) * 132 + j0];
            #pragma unroll
            for (int jj = 0; jj < 8; jj++) {
                float x = u[ii][jj];
                float m = fabsf(x) - LAM;
                ap[jj] = (m > 0.f) ? copysignf(m, x) : 0.f;
            }
        }
        __syncthreads();

        float acc[4][8] = {};
        #pragma unroll 2
        for (int i = 0; i < NB; i += 4) {
            float4 a0 = *(const float4*)&sa[(sl0 + 0) * 132 + i];
            float4 a1 = *(const float4*)&sa[(sl0 + 1) * 132 + i];
            float4 a2 = *(const float4*)&sa[(sl0 + 2) * 132 + i];
            float4 a3 = *(const float4*)&sa[(sl0 + 3) * 132 + i];
            float av[4][4] = {{a0.x, a0.y, a0.z, a0.w},
                              {a1.x, a1.y, a1.z, a1.w},
                              {a2.x, a2.y, a2.z, a2.w},
                              {a3.x, a3.y, a3.z, a3.w}};
            #pragma unroll
            for (int q = 0; q < 4; q++) {
                float4 gq0 = *(const float4*)&sG[(i + q) * 132 + j0];
                float4 gq1 = *(const float4*)&sG[(i + q) * 132 + j0 + 4];
                float gv[8] = {gq0.x, gq0.y, gq0.z, gq0.w,
                               gq1.x, gq1.y, gq1.z, gq1.w};
                #pragma unroll
                for (int ii = 0; ii < 4; ii++)
                    #pragma unroll
                    for (int jj = 0; jj < 8; jj++)
                        acc[ii][jj] += av[ii][q] * gv[jj];
            }
        }

        #pragma unroll
        for (int ii = 0; ii < 4; ii++)
            #pragma unroll
            for (int jj = 0; jj < 8; jj++)
                u[ii][jj] += (bb[ii][jj] - u[ii][jj] - acc[ii][jj]) * 0.1f;
        __syncthreads();
    }

    #pragma unroll
    for (int ii = 0; ii < 4; ii++) {
        float* op = out + (size_t)(s0 + sl0 + ii) * NB + j0;
        #pragma unroll
        for (int jj = 0; jj < 8; jj++) {
            float x = u[ii][jj];
            float m = fabsf(x) - LAM;
            op[jj] = (m > 0.f) ? copysignf(m, x) : 0.f;
        }
    }
}

// ---------------- launch ----------------
extern "C" void kernel_launch(void* const* d_in, const int* in_sizes, int n_in,
                              void* d_out, int out_size) {
    const float* audio = (const float*)d_in[0];   // (8192, 3200)
    const float* D     = (const float*)d_in[1];   // (128, 4369)
    float* out = (float*)d_out;                   // (8192, 128)

    static const size_t LCA_SMEM = (128 * 132 + 64 * 132) * sizeof(float); // 101376
    cudaFuncSetAttribute(lca_kernel, cudaFuncAttributeMaxDynamicSharedMemorySize,
                         (int)LCA_SMEM);

    permuted_kernel<<<NB, 256>>>(D);
    gram_kernel<<<64, 256>>>(D);
    stft_kernel<<<dim3(NFRM, BATCH), 128>>>(audio);
    stats_kernel<<<BATCH, 256>>>();
    bgemm_kernel<<<BATCH / 64, 256>>>();
    lca_kernel<<<BATCH / 64, 256, LCA_SMEM>>>(out);
}